// round 8
// baseline (speedup 1.0000x reference)
#include <cuda_runtime.h>
#include <cuda_bf16.h>
#include <math.h>

// ---------------- problem constants ----------------
// B=16, L=128, D=512, E=512, DI=2048, T=127, V=32000

// ---------------- scratch (device globals) ----------------
__device__ float d_emb  [2048*512];     // row m = l*16+b
__device__ float d_xgf  [2048*2048];    // enc fwd gate inputs (+bih+bhh)
__device__ float d_xgb  [2048*2048];
__device__ float d_xenc [16*128*1024];  // [b][l][2D]
__device__ float d_xenck[16*128*512];   // [b][l][D]
__device__ float d_hf[2][16*512];
__device__ float d_hb[2][16*512];
__device__ float d_cf[16*512];
__device__ float d_cb[16*512];
__device__ float d_biasF[2048];
__device__ float d_biasB[2048];
__device__ float d_attr [16*512];
__device__ float d_abase[16*2048];      // attr@W2^T + bih_d + bhh_d
__device__ float d_gbase[2032*2048];    // xemb@W1^T + abase, row m=t*16+b
__device__ float d_hdec[2][16*512];
__device__ float d_cdec[16*512];
__device__ float d_feed [16*1024];
__device__ float d_attq [16*512];
__device__ float d_sraw [16*128];
__device__ float d_hcall[2032*1536];    // [h(512), ctx(1024)]
__device__ float d_pres [2032*512];

// ---------------- math helpers ----------------
__device__ __forceinline__ float tanha(float x){            // accurate
    x = fminf(fmaxf(x, -15.f), 15.f);
    float e = __expf(2.f * x);
    return __fdividef(e - 1.f, e + 1.f);
}
__device__ __forceinline__ float sigm(float x){
    return __fdividef(1.f, 1.f + __expf(-x));
}
__device__ __forceinline__ float tanhx(float x){            // HW approx (scores only)
    float y; asm("tanh.approx.f32 %0, %1;" : "=f"(y) : "f"(x)); return y;
}
#define DOT4(a,x,w) (a) += (x).x*(w).x + (x).y*(w).y + (x).z*(w).z + (x).w*(w).w

// ---------------- prep kernels ----------------
__global__ void k_init(){
    int i = blockIdx.x*256 + threadIdx.x;            // 16384 threads
    if (i < 16*512){ d_hf[0][i]=0.f; d_hb[0][i]=0.f; d_cf[i]=0.f; d_cb[i]=0.f; }
    if (i < 16*1024) d_feed[i]=0.f;
}

__global__ void k_bias(const float* __restrict__ bihf, const float* __restrict__ bhhf,
                       const float* __restrict__ bihb, const float* __restrict__ bhhb){
    int i = blockIdx.x*256 + threadIdx.x;
    if (i < 2048){ d_biasF[i] = bihf[i] + bhhf[i]; d_biasB[i] = bihb[i] + bhhb[i]; }
}

__global__ void k_embed(const int* __restrict__ x_train, const float* __restrict__ word_emb){
    int m = blockIdx.x;                 // m = l*16+b
    int b = m & 15, l = m >> 4;
    int tok = x_train[b*128 + l];
    const float4* src = (const float4*)(word_emb + (size_t)tok*512);
    float4* dst = (float4*)(d_emb + (size_t)m*512);
    dst[threadIdx.x] = src[threadIdx.x];
}

__global__ void k_attr(const int* __restrict__ y_train, const float* __restrict__ attr_emb){
    int b = blockIdx.x;
    float4 s = make_float4(0.f,0.f,0.f,0.f);
    for (int j = 0; j < 2; j++){
        int tok = y_train[b*2 + j];
        float4 v = ((const float4*)(attr_emb + (size_t)tok*512))[threadIdx.x];
        s.x += v.x; s.y += v.y; s.z += v.z; s.w += v.w;
    }
    ((float4*)(d_attr + b*512))[threadIdx.x] = s;
}

// abase[b][n] = bih_d[n]+bhh_d[n] + attr[b] . Wih_d[n][512:1024]
__global__ void k_abase(const float* __restrict__ Wih_d,
                        const float* __restrict__ bih_d, const float* __restrict__ bhh_d){
    int p = blockIdx.x*128 + threadIdx.x;     // 32768
    int b = p & 15, n = p >> 4;
    const float4* xp = (const float4*)(d_attr + b*512);
    const float4* wp = (const float4*)(Wih_d + (size_t)n*2048 + 512);
    float acc = 0.f;
    #pragma unroll 8
    for (int k = 0; k < 128; k++){ float4 x = xp[k], w = wp[k]; DOT4(acc,x,w); }
    d_abase[b*2048 + n] = acc + bih_d[n] + bhh_d[n];
}

// ---------------- generic SGEMM: C[m][n] = sum_k A[m][k]*B[n][k] ----------------
// 128x128 tile, BK=8, 256 threads, 8x8/thread, double-buffered smem.
// N (grid.x*128) must be a multiple of 128 and K a multiple of 8 (true for all uses).
__global__ __launch_bounds__(256) void k_gemm(
    const float* __restrict__ A, int lda,
    const float* __restrict__ B, int ldb,
    float* __restrict__ C, int ldc,
    int M, int K,
    const float* __restrict__ bias,
    const float* __restrict__ bias2d,
    int act, int mode)
{
    __shared__ float As[2][8][132];
    __shared__ float Bs[2][8][132];
    const int tid = threadIdx.x;
    const int m0 = blockIdx.y * 128, n0 = blockIdx.x * 128;
    const int lm = tid >> 1, lk4 = (tid & 1) * 4;
    const bool mval = (m0 + lm) < M;
    const float* Ap = A + (size_t)(m0 + lm) * lda + lk4;
    const float* Bp = B + (size_t)(n0 + lm) * ldb + lk4;
    const int tx = tid & 15, ty = tid >> 4;

    float cr[8][8];
    #pragma unroll
    for (int i = 0; i < 8; i++)
        #pragma unroll
        for (int j = 0; j < 8; j++) cr[i][j] = 0.f;

    float4 av = mval ? *(const float4*)Ap : make_float4(0,0,0,0);
    float4 bv = *(const float4*)Bp;
    As[0][lk4+0][lm]=av.x; As[0][lk4+1][lm]=av.y; As[0][lk4+2][lm]=av.z; As[0][lk4+3][lm]=av.w;
    Bs[0][lk4+0][lm]=bv.x; Bs[0][lk4+1][lm]=bv.y; Bs[0][lk4+2][lm]=bv.z; Bs[0][lk4+3][lm]=bv.w;
    __syncthreads();

    const int nk = K >> 3;
    for (int kt = 0; kt < nk; kt++){
        const int cur = kt & 1;
        if (kt + 1 < nk){
            av = mval ? *(const float4*)(Ap + (kt+1)*8) : make_float4(0,0,0,0);
            bv = *(const float4*)(Bp + (kt+1)*8);
        }
        #pragma unroll
        for (int k = 0; k < 8; k++){
            float4 a0 = *(const float4*)&As[cur][k][ty*8];
            float4 a1 = *(const float4*)&As[cur][k][ty*8+4];
            float4 b0 = *(const float4*)&Bs[cur][k][tx*8];
            float4 b1 = *(const float4*)&Bs[cur][k][tx*8+4];
            float am[8] = {a0.x,a0.y,a0.z,a0.w,a1.x,a1.y,a1.z,a1.w};
            float bn[8] = {b0.x,b0.y,b0.z,b0.w,b1.x,b1.y,b1.z,b1.w};
            #pragma unroll
            for (int i = 0; i < 8; i++)
                #pragma unroll
                for (int j = 0; j < 8; j++) cr[i][j] += am[i]*bn[j];
        }
        if (kt + 1 < nk){
            const int nxt = cur ^ 1;
            As[nxt][lk4+0][lm]=av.x; As[nxt][lk4+1][lm]=av.y; As[nxt][lk4+2][lm]=av.z; As[nxt][lk4+3][lm]=av.w;
            Bs[nxt][lk4+0][lm]=bv.x; Bs[nxt][lk4+1][lm]=bv.y; Bs[nxt][lk4+2][lm]=bv.z; Bs[nxt][lk4+3][lm]=bv.w;
        }
        __syncthreads();
    }

    #pragma unroll
    for (int i = 0; i < 8; i++){
        int m = m0 + ty*8 + i;
        if (m >= M) continue;
        size_t rb = (mode == 0) ? (size_t)m * ldc
                                : (size_t)(m & 15) * 4064000 + (size_t)(m >> 4) * 32000;
        #pragma unroll
        for (int j4 = 0; j4 < 8; j4 += 4){
            int n = n0 + tx*8 + j4;
            float vv[4];
            #pragma unroll
            for (int j = 0; j < 4; j++){
                float x = cr[i][j4+j];
                if (bias)   x += bias[n + j];
                if (bias2d) x += bias2d[(size_t)(m & 15)*2048 + n + j];
                if (act)    x = tanha(x);
                vv[j] = x;
            }
            *(float4*)(C + rb + n) = make_float4(vv[0], vv[1], vv[2], vv[3]);
        }
    }
}

// ---------------- encoder step (fwd + bwd fused, 2-way K split) ----------------
__global__ void k_encstep(int s, const float* __restrict__ Whh_f, const float* __restrict__ Whh_b){
    int p = blockIdx.x*128 + threadIdx.x;   // 256 blocks * 128 = 32768
    int half = p & 1;
    int pair = p >> 1;                      // 0..16383
    int dir  = pair >> 13;                  // 0 fwd, 1 bwd
    int rem  = pair & 8191;
    int b = rem & 15;
    int d = rem >> 4;
    int t = dir ? (127 - s) : s;
    const float* Whh = dir ? Whh_b : Whh_f;
    const float* hprev = (dir ? d_hb[s & 1] : d_hf[s & 1]) + b*512;
    int klo = half * 256;
    const float4* hp = (const float4*)(hprev + klo);
    const float4* w0 = (const float4*)(Whh + (size_t)d*512 + klo);
    const float4* w1 = (const float4*)(Whh + (size_t)(d+512)*512 + klo);
    const float4* w2 = (const float4*)(Whh + (size_t)(d+1024)*512 + klo);
    const float4* w3 = (const float4*)(Whh + (size_t)(d+1536)*512 + klo);
    float a0=0.f,a1=0.f,a2=0.f,a3=0.f;
    #pragma unroll 8
    for (int k = 0; k < 64; k++){
        float4 x = hp[k]; float4 w;
        w=w0[k]; DOT4(a0,x,w);
        w=w1[k]; DOT4(a1,x,w);
        w=w2[k]; DOT4(a2,x,w);
        w=w3[k]; DOT4(a3,x,w);
    }
    const unsigned FULL = 0xffffffffu;
    a0 += __shfl_xor_sync(FULL, a0, 1);
    a1 += __shfl_xor_sync(FULL, a1, 1);
    a2 += __shfl_xor_sync(FULL, a2, 1);
    a3 += __shfl_xor_sync(FULL, a3, 1);
    if (half == 0){
        const float* xg = (dir ? d_xgb : d_xgf) + (size_t)(t*16 + b)*2048;
        float gi = xg[d]        + a0;
        float gf = xg[d + 512]  + a1;
        float gg = xg[d + 1024] + a2;
        float go = xg[d + 1536] + a3;
        float* cbuf = dir ? d_cb : d_cf;
        float c = cbuf[b*512 + d];
        c = sigm(gf)*c + sigm(gi)*tanha(gg);
        float h = sigm(go)*tanha(c);
        cbuf[b*512 + d] = c;
        (dir ? d_hb[(s+1)&1] : d_hf[(s+1)&1])[b*512 + d] = h;
        d_xenc[(size_t)(b*128 + t)*1024 + dir*512 + d] = h;
    }
}

// ---------------- bridge: h0 = tanh(cT @ Wb^T), c0 = cT @ Wb^T ----------------
__global__ void k_bridge(const float* __restrict__ W_bridge){
    int p = blockIdx.x*128 + threadIdx.x;   // 64*128 = 8192
    int b = p & 15, j = p >> 4;
    const float4* c0p = (const float4*)(d_cf + b*512);
    const float4* c1p = (const float4*)(d_cb + b*512);
    const float4* w0p = (const float4*)(W_bridge + (size_t)j*1024);
    const float4* w1p = (const float4*)(W_bridge + (size_t)j*1024 + 512);
    float acc = 0.f;
    #pragma unroll 8
    for (int k = 0; k < 128; k++){
        float4 x = c0p[k], w = w0p[k]; DOT4(acc,x,w);
        x = c1p[k]; w = w1p[k]; DOT4(acc,x,w);
    }
    d_cdec[b*512 + j] = acc;
    d_hdec[0][b*512 + j] = tanha(acc);
}

// ---------------- decoder kernel 1: gates + state update (4-way K split) ----------------
__global__ void k_dec_gates(int t, const float* __restrict__ Wih_d, const float* __restrict__ Whh_d){
    int p = blockIdx.x*128 + threadIdx.x;   // 256 blocks * 128 = 32768
    int q = p & 3;
    int pair = p >> 2;                      // 0..8191
    int b = pair & 15;
    int d = pair >> 4;
    float a0=0.f,a1=0.f,a2=0.f,a3=0.f;
    int lo = q*384, hi = lo + 384;          // over K = 1536 (feed 1024 + h 512)
    int flo = lo, fhi = hi < 1024 ? hi : 1024;
    if (flo < fhi){
        const float4* xp = (const float4*)(d_feed + b*1024 + flo);
        const float4* w0 = (const float4*)(Wih_d + (size_t)d*2048        + 1024 + flo);
        const float4* w1 = (const float4*)(Wih_d + (size_t)(d+512)*2048  + 1024 + flo);
        const float4* w2 = (const float4*)(Wih_d + (size_t)(d+1024)*2048 + 1024 + flo);
        const float4* w3 = (const float4*)(Wih_d + (size_t)(d+1536)*2048 + 1024 + flo);
        int n4 = (fhi - flo) >> 2;
        #pragma unroll 4
        for (int k = 0; k < n4; k++){
            float4 x = xp[k]; float4 w;
            w=w0[k]; DOT4(a0,x,w);
            w=w1[k]; DOT4(a1,x,w);
            w=w2[k]; DOT4(a2,x,w);
            w=w3[k]; DOT4(a3,x,w);
        }
    }
    int hlo = lo > 1024 ? lo : 1024, hhi = hi;
    if (hlo < hhi){
        int k0 = hlo - 1024;
        const float4* xp = (const float4*)(d_hdec[t & 1] + b*512 + k0);
        const float4* w0 = (const float4*)(Whh_d + (size_t)d*512        + k0);
        const float4* w1 = (const float4*)(Whh_d + (size_t)(d+512)*512  + k0);
        const float4* w2 = (const float4*)(Whh_d + (size_t)(d+1024)*512 + k0);
        const float4* w3 = (const float4*)(Whh_d + (size_t)(d+1536)*512 + k0);
        int n4 = (hhi - hlo) >> 2;
        #pragma unroll 4
        for (int k = 0; k < n4; k++){
            float4 x = xp[k]; float4 w;
            w=w0[k]; DOT4(a0,x,w);
            w=w1[k]; DOT4(a1,x,w);
            w=w2[k]; DOT4(a2,x,w);
            w=w3[k]; DOT4(a3,x,w);
        }
    }
    const unsigned FULL = 0xffffffffu;
    a0 += __shfl_xor_sync(FULL,a0,1); a0 += __shfl_xor_sync(FULL,a0,2);
    a1 += __shfl_xor_sync(FULL,a1,1); a1 += __shfl_xor_sync(FULL,a1,2);
    a2 += __shfl_xor_sync(FULL,a2,1); a2 += __shfl_xor_sync(FULL,a2,2);
    a3 += __shfl_xor_sync(FULL,a3,1); a3 += __shfl_xor_sync(FULL,a3,2);
    if (q == 0){
        const float* gb = d_gbase + (size_t)(t*16 + b)*2048;
        float gi = gb[d]        + a0;
        float gf = gb[d + 512]  + a1;
        float gg = gb[d + 1024] + a2;
        float go = gb[d + 1536] + a3;
        float c = d_cdec[b*512 + d];
        c = sigm(gf)*c + sigm(gi)*tanha(gg);
        float h = sigm(go)*tanha(c);
        d_cdec[b*512 + d] = c;
        d_hdec[(t+1)&1][b*512 + d] = h;
        d_hcall[(size_t)(t*16 + b)*1536 + d] = h;
    }
}

// ---------------- decoder kernel 2: q = h @ W_trg^T + b_trg ----------------
__global__ void k_dec_q(int t, const float* __restrict__ W_trg, const float* __restrict__ b_trg){
    int p = blockIdx.x*128 + threadIdx.x;   // 64*128 = 8192
    int b = p & 15, j = p >> 4;
    const float4* hp = (const float4*)(d_hdec[(t+1)&1] + b*512);
    const float4* wp = (const float4*)(W_trg + (size_t)j*512);
    float acc = 0.f;
    #pragma unroll 8
    for (int k = 0; k < 128; k++){ float4 x = hp[k], w = wp[k]; DOT4(acc,x,w); }
    d_attq[b*512 + j] = acc + b_trg[j];
}

// ---------------- decoder kernel 3: scores[b][l] ----------------
__global__ void k_dec_scores(const float* __restrict__ w_att, const float* __restrict__ b_att){
    __shared__ float q_s[512];
    __shared__ float w_s[512];
    int b = blockIdx.x & 15, lc = blockIdx.x >> 4;   // 128 blocks
    int tid = threadIdx.x;                            // 256
    for (int i = tid; i < 512; i += 256){ q_s[i] = d_attq[b*512 + i]; w_s[i] = w_att[i]; }
    __syncthreads();
    int lsub = tid >> 4, lane = tid & 15;
    int l = lc*16 + lsub;
    const float* xk = d_xenck + (size_t)(b*128 + l)*512;
    float sum = 0.f;
    #pragma unroll 8
    for (int d = lane; d < 512; d += 16) sum += tanhx(xk[d] + q_s[d]) * w_s[d];
    #pragma unroll
    for (int o = 8; o; o >>= 1) sum += __shfl_xor_sync(0xffffffffu, sum, o);
    if (lane == 0) d_sraw[b*128 + l] = sum + b_att[0];
}

// ---------------- decoder kernel 4: softmax + ctx ----------------
__global__ void k_dec_ctx(int t){
    __shared__ float red[128];
    __shared__ float w_s[128];
    int b = blockIdx.x & 15, jc = blockIdx.x >> 4;   // 128 blocks * 128 threads
    int tid = threadIdx.x;
    float s = d_sraw[b*128 + tid];
    red[tid] = s; __syncthreads();
    #pragma unroll
    for (int o = 64; o; o >>= 1){ if (tid < o) red[tid] = fmaxf(red[tid], red[tid + o]); __syncthreads(); }
    float mx = red[0]; __syncthreads();
    float e = __expf(s - mx);
    red[tid] = e; __syncthreads();
    #pragma unroll
    for (int o = 64; o; o >>= 1){ if (tid < o) red[tid] += red[tid + o]; __syncthreads(); }
    float inv = __fdividef(1.f, red[0]);
    w_s[tid] = e * inv; __syncthreads();
    int j = jc*128 + tid;
    const float* xe = d_xenc + (size_t)b*128*1024 + j;
    float acc = 0.f;
    #pragma unroll 8
    for (int l = 0; l < 128; l++) acc += w_s[l] * xe[(size_t)l*1024];
    d_feed[b*1024 + j] = acc;
    d_hcall[(size_t)(t*16 + b)*1536 + 512 + j] = acc;
}

// ---------------- host ----------------
extern "C" void kernel_launch(void* const* d_in, const int* in_sizes, int n_in,
                              void* d_out, int out_size){
    const int*   x_train  = (const int*)  d_in[0];
    const int*   y_train  = (const int*)  d_in[2];
    const float* word_emb = (const float*)d_in[3];
    const float* attr_emb = (const float*)d_in[4];
    const float* Wih_f    = (const float*)d_in[5];
    const float* Whh_f    = (const float*)d_in[6];
    const float* bih_f    = (const float*)d_in[7];
    const float* bhh_f    = (const float*)d_in[8];
    const float* Wih_b    = (const float*)d_in[9];
    const float* Whh_b    = (const float*)d_in[10];
    const float* bih_b    = (const float*)d_in[11];
    const float* bhh_b    = (const float*)d_in[12];
    const float* W_bridge = (const float*)d_in[13];
    const float* W_enc2k  = (const float*)d_in[14];
    const float* Wih_d    = (const float*)d_in[15];
    const float* Whh_d    = (const float*)d_in[16];
    const float* bih_d    = (const float*)d_in[17];
    const float* bhh_d    = (const float*)d_in[18];
    const float* W_trg    = (const float*)d_in[19];
    const float* b_trg    = (const float*)d_in[20];
    const float* w_att    = (const float*)d_in[21];
    const float* b_att    = (const float*)d_in[22];
    const float* W_ro     = (const float*)d_in[23];
    const float* W_read   = (const float*)d_in[24];
    float* out = (float*)d_out;

    float *emb, *xgf, *xgb, *xenc, *xenck, *gbase, *abase, *hcall, *pres, *biasF, *biasB;
    cudaGetSymbolAddress((void**)&emb,   d_emb);
    cudaGetSymbolAddress((void**)&xgf,   d_xgf);
    cudaGetSymbolAddress((void**)&xgb,   d_xgb);
    cudaGetSymbolAddress((void**)&xenc,  d_xenc);
    cudaGetSymbolAddress((void**)&xenck, d_xenck);
    cudaGetSymbolAddress((void**)&gbase, d_gbase);
    cudaGetSymbolAddress((void**)&abase, d_abase);
    cudaGetSymbolAddress((void**)&hcall, d_hcall);
    cudaGetSymbolAddress((void**)&pres,  d_pres);
    cudaGetSymbolAddress((void**)&biasF, d_biasF);
    cudaGetSymbolAddress((void**)&biasB, d_biasB);

    // prep
    k_init <<<64, 256>>>();
    k_bias <<<8, 256>>>(bih_f, bhh_f, bih_b, bhh_b);
    k_embed<<<2048, 128>>>(x_train, word_emb);
    k_attr <<<16, 128>>>(y_train, attr_emb);

    // encoder gate-input precompute: xg = emb @ Wih^T + (bih+bhh)
    k_gemm<<<dim3(16,16),256>>>(emb,512, Wih_f,512, xgf,2048, 2048,512, biasF,0, 0,0);
    k_gemm<<<dim3(16,16),256>>>(emb,512, Wih_b,512, xgb,2048, 2048,512, biasB,0, 0,0);

    // encoder recurrence (fwd+bwd fused)
    for (int s = 0; s < 128; s++)
        k_encstep<<<256,128>>>(s, Whh_f, Whh_b);

    // bridge + x_enc_k + decoder gate-base precompute
    k_bridge<<<64,128>>>(W_bridge);
    k_gemm<<<dim3(4,16),256>>>(xenc,1024, W_enc2k,1024, xenck,512, 2048,1024, 0,0, 0,0);
    k_abase<<<256,128>>>(Wih_d, bih_d, bhh_d);
    k_gemm<<<dim3(16,16),256>>>(emb,512, Wih_d,2048, gbase,2048, 2032,512, 0,abase, 0,0);

    // decoder recurrence
    for (int t = 0; t < 127; t++){
        k_dec_gates <<<256,128>>>(t, Wih_d, Whh_d);
        k_dec_q     <<<64,128>>>(t, W_trg, b_trg);
        k_dec_scores<<<128,256>>>(w_att, b_att);
        k_dec_ctx   <<<128,128>>>(t);
    }

    // pre = tanh([h,ctx] @ W_ro^T), then logits = pre @ W_read^T -> out[b][t][v]
    k_gemm<<<dim3(4,16),256>>>(hcall,1536, W_ro,1536, pres,512, 2032,1536, 0,0, 1,0);
    k_gemm<<<dim3(250,16),256>>>(pres,512, W_read,512, out,0, 2032,512, 0,0, 0,1);
}